// round 3
// baseline (speedup 1.0000x reference)
#include <cuda_runtime.h>
#include <math.h>

#define BB 8
#define CC 64
#define NN 4096
#define KK 32
#define ROWS_TOT (BB*NN)   // 32768
#define EPS 1e-5f

// ---------------- scratch (device globals; no runtime alloc) ----------------
static __device__ float g_feat[ROWS_TOT*CC];
static __device__ float g_sq[ROWS_TOT];
static __device__ float g_q[ROWS_TOT*CC];
static __device__ float g_k[ROWS_TOT*CC];
static __device__ float g_v[ROWS_TOT*CC];
static __device__ float g_dist[(size_t)ROWS_TOT*NN];   // 512MB
static __device__ int   g_idx[ROWS_TOT*KK];
static __device__ float g_y1[ROWS_TOT*CC];
static __device__ float g_y2[ROWS_TOT*CC];
static __device__ float g_part[2*256*CC];
static __device__ float g_scale[CC];
static __device__ float g_bias[CC];

// ---------------- 1) transpose + sq + Q/K/V projections ---------------------
// grid 8192 blocks x 256 threads; 4 points per block.
// dynamic smem: wqt/wkt/wvt (transposed, 4096 fl each) + f (256 fl) = 50176 B
__global__ void k_prep(const float* __restrict__ x,
                       const float* __restrict__ wq,
                       const float* __restrict__ wk,
                       const float* __restrict__ wv)
{
    extern __shared__ float sh[];
    float* wqt = sh;            // [i*64 + o]
    float* wkt = sh + 4096;
    float* wvt = sh + 8192;
    float* f   = sh + 12288;    // [g*64 + c]
    __shared__ float sqs[8];

    int t = threadIdx.x;
    for (int l = t; l < 4096; l += 256) {
        int o = l >> 6, i = l & 63;
        wqt[i*64 + o] = wq[l];
        wkt[i*64 + o] = wk[l];
        wvt[i*64 + o] = wv[l];
    }
    int g = t >> 6, c = t & 63;
    int p = blockIdx.x * 4 + g;
    int b = p >> 12, n = p & 4095;
    float val = x[((size_t)b*64 + c)*4096 + n];
    f[g*64 + c] = val;
    float vsq = val * val;
    #pragma unroll
    for (int o = 16; o; o >>= 1) vsq += __shfl_xor_sync(0xffffffffu, vsq, o);
    if ((t & 31) == 0) sqs[t >> 5] = vsq;
    __syncthreads();
    if (c == 0) g_sq[p] = sqs[g*2] + sqs[g*2 + 1];

    const float* fr = f + g*64;
    float aq = 0.f, ak = 0.f, av = 0.f;
    #pragma unroll
    for (int i = 0; i < 64; i += 4) {
        float4 f4 = *(const float4*)&fr[i];
        aq += f4.x*wqt[(i  )*64+c] + f4.y*wqt[(i+1)*64+c] + f4.z*wqt[(i+2)*64+c] + f4.w*wqt[(i+3)*64+c];
        ak += f4.x*wkt[(i  )*64+c] + f4.y*wkt[(i+1)*64+c] + f4.z*wkt[(i+2)*64+c] + f4.w*wkt[(i+3)*64+c];
        av += f4.x*wvt[(i  )*64+c] + f4.y*wvt[(i+1)*64+c] + f4.z*wvt[(i+2)*64+c] + f4.w*wvt[(i+3)*64+c];
    }
    int pc = p*64 + c;
    g_feat[pc] = val;
    g_q[pc] = aq; g_k[pc] = ak; g_v[pc] = av;
}

// ---------------- 2) gram: neg_d = 2 F F^T - sq_n - sq_m --------------------
// grid (64, 64, 8), block 256 (16x16, 4x4 outputs/thread). fp32 exact.
__global__ __launch_bounds__(256) void k_gram()
{
    __shared__ float Ast[64*68];   // [kk*68 + r]  (transposed, padded)
    __shared__ float Bst[64*68];
    __shared__ float sqA[64], sqB[64];

    int b    = blockIdx.z;
    int row0 = blockIdx.y << 6;
    int col0 = blockIdx.x << 6;
    int t  = threadIdx.x;
    int tx = t & 15, ty = t >> 4;

    const float* fb = g_feat + (size_t)b * NN * CC;
    for (int l = t; l < 4096; l += 256) {
        int r = l >> 6, c = l & 63;
        Ast[c*68 + r] = fb[(row0 + r)*64 + c];
        Bst[c*68 + r] = fb[(col0 + r)*64 + c];
    }
    if (t < 64) {
        sqA[t] = g_sq[b*NN + row0 + t];
        sqB[t] = g_sq[b*NN + col0 + t];
    }
    __syncthreads();

    float acc[4][4];
    #pragma unroll
    for (int i = 0; i < 4; i++)
        #pragma unroll
        for (int j = 0; j < 4; j++) acc[i][j] = 0.f;

    #pragma unroll
    for (int kk = 0; kk < 64; kk++) {
        float4 a4 = *(const float4*)&Ast[kk*68 + ty*4];
        float4 b4 = *(const float4*)&Bst[kk*68 + tx*4];
        float a[4] = {a4.x, a4.y, a4.z, a4.w};
        float bb[4] = {b4.x, b4.y, b4.z, b4.w};
        #pragma unroll
        for (int i = 0; i < 4; i++)
            #pragma unroll
            for (int j = 0; j < 4; j++) acc[i][j] += a[i]*bb[j];
    }

    #pragma unroll
    for (int i = 0; i < 4; i++) {
        int r = row0 + ty*4 + i;
        float sa = sqA[ty*4 + i];
        float4 o;
        o.x = 2.f*acc[i][0] - sa - sqB[tx*4 + 0];
        o.y = 2.f*acc[i][1] - sa - sqB[tx*4 + 1];
        o.z = 2.f*acc[i][2] - sa - sqB[tx*4 + 2];
        o.w = 2.f*acc[i][3] - sa - sqB[tx*4 + 3];
        *(float4*)&g_dist[((size_t)b << 24) + (size_t)r*4096 + col0 + tx*4] = o;
    }
}

// ---------------- 3) top-K: iterative block argmax (set-invariant) ----------
// grid 32768 x 256; each thread owns 16 candidates in registers.
__global__ __launch_bounds__(256) void k_topk()
{
    int row = blockIdx.x;
    int t = threadIdx.x;
    const float* dr = g_dist + (size_t)row * 4096;

    float v[16];
    #pragma unroll
    for (int j = 0; j < 16; j++) v[j] = dr[j*256 + t];
    float bv = -3.4e38f; int bj = 0;
    #pragma unroll
    for (int j = 0; j < 16; j++) if (v[j] > bv) { bv = v[j]; bj = j; }

    __shared__ unsigned long long wred[8];
    __shared__ unsigned long long winner;
    int lane = t & 31, wid = t >> 5;

    for (int it = 0; it < 32; it++) {
        unsigned ku = __float_as_uint(bv);
        ku = (ku & 0x80000000u) ? ~ku : (ku | 0x80000000u);
        unsigned long long pk = ((unsigned long long)ku << 32) | (unsigned)(bj*256 + t);
        #pragma unroll
        for (int o = 16; o; o >>= 1) {
            unsigned long long q = __shfl_xor_sync(0xffffffffu, pk, o);
            if (q > pk) pk = q;
        }
        if (lane == 0) wred[wid] = pk;
        __syncthreads();
        if (wid == 0) {
            unsigned long long p2 = wred[lane & 7];
            #pragma unroll
            for (int o = 4; o; o >>= 1) {
                unsigned long long q = __shfl_xor_sync(0xffffffffu, p2, o);
                if (q > p2) p2 = q;
            }
            if (lane == 0) winner = p2;
        }
        __syncthreads();
        unsigned long long w = winner;
        int m = (int)(w & 0xFFFFFFFFu);
        if (t == 0) g_idx[row*KK + it] = m;
        if ((m & 255) == t) {
            v[m >> 8] = -3.4e38f;
            bv = -3.4e38f; bj = 0;
            #pragma unroll
            for (int j = 0; j < 16; j++) if (v[j] > bv) { bv = v[j]; bj = j; }
        }
        __syncthreads();
    }
}

// ---------------- 4) attention via Kf/Vf diffs + residual -------------------
// grid 32768 x 128; warp h = head h.
__global__ __launch_bounds__(128) void k_attn()
{
    int p = blockIdx.x;
    int b = p >> 12;
    int t = threadIdx.x;

    __shared__ float Kd[32*65], Vd[32*65];
    __shared__ float s_q[64], s_kp[64], s_vp[64], s_f[64];
    __shared__ float s_at[128];
    __shared__ int   s_idx[32];

    if (t < 64) {
        s_q[t]  = g_q[p*64 + t];
        s_kp[t] = g_k[p*64 + t];
        s_vp[t] = g_v[p*64 + t];
        s_f[t]  = g_feat[p*64 + t];
    } else if (t < 96) {
        s_idx[t - 64] = g_idx[p*KK + (t - 64)];
    }
    __syncthreads();

    int base = (b << 12) * 64;
    for (int e = t; e < 2048; e += 128) {
        int j = e >> 6, c = e & 63;
        int nb = s_idx[j];
        Kd[j*65 + c] = g_k[base + nb*64 + c] - s_kp[c];
        Vd[j*65 + c] = g_v[base + nb*64 + c] - s_vp[c];
    }
    __syncthreads();

    int h = t >> 5, j = t & 31;
    float e = 0.f;
    #pragma unroll
    for (int d = 0; d < 16; d++) e += s_q[h*16 + d] * Kd[j*65 + h*16 + d];
    e *= 0.25f;   // 1/sqrt(16)
    float m = e;
    #pragma unroll
    for (int o = 16; o; o >>= 1) m = fmaxf(m, __shfl_xor_sync(0xffffffffu, m, o));
    float ex = expf(e - m);
    float s = ex;
    #pragma unroll
    for (int o = 16; o; o >>= 1) s += __shfl_xor_sync(0xffffffffu, s, o);
    s_at[t] = ex / s;
    __syncthreads();

    if (t < 64) {
        int hh = t >> 4;
        float acc = 0.f;
        #pragma unroll
        for (int jj = 0; jj < 32; jj++) acc += s_at[hh*32 + jj] * Vd[jj*65 + t];
        g_y1[p*64 + t] = s_f[t] + acc;
    }
}

// ---------------- 5) BatchNorm stats: two-stage deterministic ---------------
__global__ void k_bnstat1(int which)
{
    const float* y = which ? g_y2 : g_y1;
    int g = blockIdx.x, t = threadIdx.x;
    int c = t & 63, grp = t >> 6;
    float s = 0.f, ss = 0.f;
    int r0 = g * 128;
    for (int r = grp; r < 128; r += 4) {
        float v = y[(size_t)(r0 + r)*64 + c];
        s += v; ss += v*v;
    }
    __shared__ float sh0[4][64], sh1[4][64];
    sh0[grp][c] = s; sh1[grp][c] = ss;
    __syncthreads();
    if (grp == 0) {
        s  = sh0[0][c] + sh0[1][c] + sh0[2][c] + sh0[3][c];
        ss = sh1[0][c] + sh1[1][c] + sh1[2][c] + sh1[3][c];
        g_part[g*64 + c]         = s;
        g_part[16384 + g*64 + c] = ss;
    }
}

__global__ void k_bnstat2(const float* __restrict__ gamma,
                          const float* __restrict__ beta)
{
    int c = threadIdx.x;   // 64
    float s = 0.f, ss = 0.f;
    for (int g = 0; g < 256; g++) {
        s  += g_part[g*64 + c];
        ss += g_part[16384 + g*64 + c];
    }
    float mean = s * (1.f/32768.f);
    float var  = ss * (1.f/32768.f) - mean*mean;   // biased, as torch/jax ref
    float sc = gamma[c] * rsqrtf(var + EPS);
    g_scale[c] = sc;
    g_bias[c]  = beta[c] - mean*sc;
}

// ---------------- 6) BN1-apply + MLP + residual ------------------------------
// grid 1024 x 256; 32 rows/block; dynamic smem 172032 B.
__global__ __launch_bounds__(256) void k_mlp(const float* __restrict__ w1,
                                             const float* __restrict__ w2)
{
    extern __shared__ float sm[];
    float* w1t = sm;            // [i*256 + o]
    float* w2t = sm + 16384;    // [o*64  + c]
    float* f1s = sm + 32768;    // [r*64  + c]
    float* hs  = sm + 34816;    // [r*256 + o]

    int t = threadIdx.x;
    int row0 = blockIdx.x * 32;

    for (int l = t; l < 16384; l += 256) {
        int o = l >> 6, i = l & 63;
        w1t[i*256 + o] = w1[l];
    }
    for (int l = t; l < 16384; l += 256) {
        int c = l >> 8, o = l & 255;
        w2t[o*64 + c] = w2[l];
    }
    for (int l = t; l < 2048; l += 256) {
        int c = l & 63;
        f1s[l] = g_y1[(size_t)row0*64 + l] * g_scale[c] + g_bias[c];
    }
    __syncthreads();

    // phase 1: hid = f1 @ w1^T, LeakyReLU(0.2)
    float acc[32];
    #pragma unroll
    for (int r = 0; r < 32; r++) acc[r] = 0.f;
    int o = t;
    for (int i = 0; i < 64; i += 4) {
        float wa = w1t[(i  )*256 + o];
        float wb = w1t[(i+1)*256 + o];
        float wc = w1t[(i+2)*256 + o];
        float wd = w1t[(i+3)*256 + o];
        #pragma unroll
        for (int r = 0; r < 32; r++) {
            float4 f4 = *(const float4*)&f1s[r*64 + i];
            acc[r] += f4.x*wa + f4.y*wb + f4.z*wc + f4.w*wd;
        }
    }
    #pragma unroll
    for (int r = 0; r < 32; r++) {
        float h = acc[r];
        hs[r*256 + o] = (h > 0.f) ? h : 0.2f*h;
    }
    __syncthreads();

    // phase 2: ff = hid @ w2^T; y2 = f1 + ff
    int c = t & 63, rg = t >> 6;
    float a2[8];
    #pragma unroll
    for (int rr = 0; rr < 8; rr++) a2[rr] = 0.f;
    for (int oo = 0; oo < 256; oo += 4) {
        float u0 = w2t[(oo  )*64 + c];
        float u1 = w2t[(oo+1)*64 + c];
        float u2 = w2t[(oo+2)*64 + c];
        float u3 = w2t[(oo+3)*64 + c];
        #pragma unroll
        for (int rr = 0; rr < 8; rr++) {
            float4 h4 = *(const float4*)&hs[(rg*8 + rr)*256 + oo];
            a2[rr] += h4.x*u0 + h4.y*u1 + h4.z*u2 + h4.w*u3;
        }
    }
    #pragma unroll
    for (int rr = 0; rr < 8; rr++) {
        int r = rg*8 + rr;
        g_y2[(size_t)(row0 + r)*64 + c] = f1s[r*64 + c] + a2[rr];
    }
}

// ---------------- 7) BN2-apply + transpose to (B, C, N) ---------------------
// grid (128, 8) x 256
__global__ void k_out(float* __restrict__ out)
{
    __shared__ float tile[32*65];
    int b  = blockIdx.y;
    int n0 = blockIdx.x * 32;
    int t  = threadIdx.x;

    for (int l = t; l < 2048; l += 256) {
        int nl = l >> 6, c = l & 63;
        tile[nl*65 + c] = g_y2[((size_t)b*NN + n0 + nl)*64 + c] * g_scale[c] + g_bias[c];
    }
    __syncthreads();
    for (int l = t; l < 2048; l += 256) {
        int nl = l & 31, c = l >> 5;
        out[((size_t)b*64 + c)*4096 + n0 + nl] = tile[nl*65 + c];
    }
}

// ---------------- launch -----------------------------------------------------
extern "C" void kernel_launch(void* const* d_in, const int* in_sizes, int n_in,
                              void* d_out, int out_size)
{
    const float* x  = (const float*)d_in[0];
    const float* wq = (const float*)d_in[1];
    const float* wk = (const float*)d_in[2];
    const float* wv = (const float*)d_in[3];
    const float* w1 = (const float*)d_in[4];
    const float* w2 = (const float*)d_in[5];
    const float* g1 = (const float*)d_in[6];
    const float* b1 = (const float*)d_in[7];
    const float* g2 = (const float*)d_in[8];
    const float* b2 = (const float*)d_in[9];
    float* out = (float*)d_out;

    cudaFuncSetAttribute(k_prep, cudaFuncAttributeMaxDynamicSharedMemorySize, 50176);
    cudaFuncSetAttribute(k_mlp,  cudaFuncAttributeMaxDynamicSharedMemorySize, 172032);

    k_prep<<<ROWS_TOT/4, 256, 50176>>>(x, wq, wk, wv);
    dim3 gg(NN/64, NN/64, BB);
    k_gram<<<gg, 256>>>();
    k_topk<<<ROWS_TOT, 256>>>();
    k_attn<<<ROWS_TOT, 128>>>();
    k_bnstat1<<<256, 256>>>(0);
    k_bnstat2<<<1, 64>>>(g1, b1);
    k_mlp<<<ROWS_TOT/32, 256, 172032>>>(w1, w2);
    k_bnstat1<<<256, 256>>>(1);
    k_bnstat2<<<1, 64>>>(g2, b2);
    k_out<<<dim3(NN/32, BB), 256>>>(out);
}